// round 2
// baseline (speedup 1.0000x reference)
#include <cuda_runtime.h>

#define TABLE_ROWS 1025
#define HIDDEN     128
#define SEQ        512
#define BATCH      2
#define MAXSEQ     512

// Scratch for the projected tables (allocation-free rule: device globals).
__device__ float g_Ass[TABLE_ROWS * HIDDEN];   // pe_ss @ W[:, :128]^T + bias
__device__ float g_Aee[TABLE_ROWS * HIDDEN];   // pe_ee @ W[:, 128:]^T

// ---------------------------------------------------------------------------
// Kernel 1: project the 1025-row tables through the linear layer.
// grid = (ceil(1025/4), 2), block = 128 threads (thread = output h).
// 4 rows per block: shorter FMA chain per warp, 514 blocks for parallelism.
// ---------------------------------------------------------------------------
__global__ void __launch_bounds__(128)
project_tables_kernel(const float* __restrict__ pe_ss,
                      const float* __restrict__ pe_ee,
                      const float* __restrict__ W,
                      const float* __restrict__ bias)
{
    const int sel = blockIdx.y;            // 0 -> ss, 1 -> ee
    const int t0  = blockIdx.x * 4;
    const int h   = threadIdx.x;           // 0..127

    const float* __restrict__ pe = sel ? pe_ee : pe_ss;
    float* __restrict__ outA     = sel ? g_Aee : g_Ass;

    __shared__ float pe_sm[4][HIDDEN];

    #pragma unroll
    for (int r = 0; r < 4; r++) {
        int t = t0 + r;
        pe_sm[r][h] = (t < TABLE_ROWS) ? pe[(size_t)t * HIDDEN + h] : 0.0f;
    }
    __syncthreads();

    float acc[4];
    const float binit = sel ? 0.0f : bias[h];
    #pragma unroll
    for (int r = 0; r < 4; r++) acc[r] = binit;

    // W is [H, 2H] row-major; thread h uses W[h, sel*128 : sel*128+128].
    const float4* __restrict__ W4 =
        reinterpret_cast<const float4*>(W + (size_t)h * (2 * HIDDEN) + sel * HIDDEN);

    #pragma unroll 8
    for (int kg = 0; kg < HIDDEN / 4; kg++) {
        const float4 w = W4[kg];
        #pragma unroll
        for (int r = 0; r < 4; r++) {
            const float4 p = reinterpret_cast<const float4*>(pe_sm[r])[kg]; // broadcast
            acc[r] += w.x * p.x + w.y * p.y + w.z * p.z + w.w * p.w;
        }
    }

    #pragma unroll
    for (int r = 0; r < 4; r++) {
        int t = t0 + r;
        if (t < TABLE_ROWS) outA[(size_t)t * HIDDEN + h] = acc[r];
    }
}

// ---------------------------------------------------------------------------
// Kernel 2: out[b,i,j,:] = relu(A_ss[ps[i]-ps[j]+512] + A_ee[pe[i]-pe[j]+512])
// grid = B*SEQ blocks (one per (b,i)), block = 256 threads = 8 warps.
// Index arrays built once in SMEM; each warp owns a contiguous 64-row chunk
// of j, 4-way unrolled so 8 independent LDG.128 are in flight per iteration.
// Output written with streaming stores (write-once, keep L1 for the tables).
// ---------------------------------------------------------------------------
__device__ __forceinline__ void stcs4(float4* p, float4 v)
{
    asm volatile("st.global.cs.v4.f32 [%0], {%1, %2, %3, %4};"
                 :: "l"(p), "f"(v.x), "f"(v.y), "f"(v.z), "f"(v.w) : "memory");
}

__global__ void __launch_bounds__(256)
fuse_gather_kernel(const int* __restrict__ pos_s,
                   const int* __restrict__ pos_e,
                   float* __restrict__ out)
{
    const int bi = blockIdx.x;          // b*SEQ + i
    const int b  = bi >> 9;
    const int i  = bi & (SEQ - 1);

    __shared__ int iss_sm[SEQ];
    __shared__ int iee_sm[SEQ];

    // First pass: stage raw positions.
    for (int j = threadIdx.x; j < SEQ; j += blockDim.x) {
        iss_sm[j] = pos_s[b * SEQ + j];
        iee_sm[j] = pos_e[b * SEQ + j];
    }
    __syncthreads();

    const int psi = iss_sm[i];
    const int pei = iee_sm[i];
    __syncthreads();

    // Second pass: convert to row offsets (in float4 units).
    for (int j = threadIdx.x; j < SEQ; j += blockDim.x) {
        iss_sm[j] = (psi - iss_sm[j] + MAXSEQ) * (HIDDEN / 4);
        iee_sm[j] = (pei - iee_sm[j] + MAXSEQ) * (HIDDEN / 4);
    }
    __syncthreads();

    const int warp = threadIdx.x >> 5;
    const int lane = threadIdx.x & 31;

    const float4* __restrict__ Ass4 = reinterpret_cast<const float4*>(g_Ass);
    const float4* __restrict__ Aee4 = reinterpret_cast<const float4*>(g_Aee);
    float4* __restrict__ out4 =
        reinterpret_cast<float4*>(out + (size_t)bi * SEQ * HIDDEN) + lane;

    const int j0 = warp * 64;           // each warp owns j in [j0, j0+64)

    #pragma unroll 2
    for (int jj = 0; jj < 64; jj += 4) {
        const int j = j0 + jj;

        // Issue all 8 gathers before consuming any (MLP = 8).
        const float4 a0 = Ass4[iss_sm[j + 0] + lane];
        const float4 e0 = Aee4[iee_sm[j + 0] + lane];
        const float4 a1 = Ass4[iss_sm[j + 1] + lane];
        const float4 e1 = Aee4[iee_sm[j + 1] + lane];
        const float4 a2 = Ass4[iss_sm[j + 2] + lane];
        const float4 e2 = Aee4[iee_sm[j + 2] + lane];
        const float4 a3 = Ass4[iss_sm[j + 3] + lane];
        const float4 e3 = Aee4[iee_sm[j + 3] + lane];

        float4 r0, r1, r2, r3;
        r0.x = fmaxf(a0.x + e0.x, 0.0f); r0.y = fmaxf(a0.y + e0.y, 0.0f);
        r0.z = fmaxf(a0.z + e0.z, 0.0f); r0.w = fmaxf(a0.w + e0.w, 0.0f);
        r1.x = fmaxf(a1.x + e1.x, 0.0f); r1.y = fmaxf(a1.y + e1.y, 0.0f);
        r1.z = fmaxf(a1.z + e1.z, 0.0f); r1.w = fmaxf(a1.w + e1.w, 0.0f);
        r2.x = fmaxf(a2.x + e2.x, 0.0f); r2.y = fmaxf(a2.y + e2.y, 0.0f);
        r2.z = fmaxf(a2.z + e2.z, 0.0f); r2.w = fmaxf(a2.w + e2.w, 0.0f);
        r3.x = fmaxf(a3.x + e3.x, 0.0f); r3.y = fmaxf(a3.y + e3.y, 0.0f);
        r3.z = fmaxf(a3.z + e3.z, 0.0f); r3.w = fmaxf(a3.w + e3.w, 0.0f);

        stcs4(out4 + (j + 0) * (HIDDEN / 4), r0);
        stcs4(out4 + (j + 1) * (HIDDEN / 4), r1);
        stcs4(out4 + (j + 2) * (HIDDEN / 4), r2);
        stcs4(out4 + (j + 3) * (HIDDEN / 4), r3);
    }
}

// ---------------------------------------------------------------------------
// Inputs (metadata order): 0 pos_s [B,S] i32, 1 pos_e [B,S] i32,
// 2 pe_ss [1025,128] f32, 3 pe_se (unused), 4 pe_es (unused),
// 5 pe_ee [1025,128] f32, 6 W [128,256] f32, 7 b [128] f32.
// Output: [B,S,S,H] f32.
// ---------------------------------------------------------------------------
extern "C" void kernel_launch(void* const* d_in, const int* in_sizes, int n_in,
                              void* d_out, int out_size)
{
    const int*   pos_s = (const int*)d_in[0];
    const int*   pos_e = (const int*)d_in[1];
    const float* pe_ss = (const float*)d_in[2];
    const float* pe_ee = (const float*)d_in[5];
    const float* W     = (const float*)d_in[6];
    const float* bias  = (const float*)d_in[7];
    float*       out   = (float*)d_out;

    dim3 grid1((TABLE_ROWS + 3) / 4, 2);
    project_tables_kernel<<<grid1, 128>>>(pe_ss, pe_ee, W, bias);

    fuse_gather_kernel<<<BATCH * SEQ, 256>>>(pos_s, pos_e, out);
}

// round 3
// speedup vs baseline: 1.0564x; 1.0564x over previous
#include <cuda_runtime.h>

#define TABLE_ROWS 1025
#define HIDDEN     128
#define SEQ        512
#define BATCH      2
#define MAXSEQ     512

// Scratch for the projected tables (allocation-free rule: device globals).
__device__ float g_Ass[TABLE_ROWS * HIDDEN];   // pe_ss @ W[:, :128]^T + bias
__device__ float g_Aee[TABLE_ROWS * HIDDEN];   // pe_ee @ W[:, 128:]^T

// Packed dual-FMA (Blackwell f32x2) — two independent f32 MACs per instruction.
#define FFMA2(acc, a, b) \
    asm("fma.rn.f32x2 %0, %1, %2, %3;" : "=l"(acc) : "l"(a), "l"(b), "l"(acc))

// ---------------------------------------------------------------------------
// Kernel 1: project the 1025-row tables through the linear layer.
//   A_ss[t,h] = dot(pe_ss[t,:], W[h, 0:128])   + bias[h]
//   A_ee[t,h] = dot(pe_ee[t,:], W[h, 128:256])
// grid = (ceil(1025/16), 2) = 130 blocks -> single wave on 148 SMs.
// block = 128 threads (thread = output column h). 16 table rows per block.
// K-dim processed in packed f32x2 pairs: 1024 FFMA2/thread instead of 2048
// scalar FFMA. pe rows live in SMEM as 64-bit pairs (broadcast LDS, N=1).
// ---------------------------------------------------------------------------
__global__ void __launch_bounds__(128)
project_tables_kernel(const float* __restrict__ pe_ss,
                      const float* __restrict__ pe_ee,
                      const float* __restrict__ W,
                      const float* __restrict__ bias)
{
    const int sel = blockIdx.y;            // 0 -> ss, 1 -> ee
    const int t0  = blockIdx.x * 16;
    const int h   = threadIdx.x;           // 0..127

    const float* __restrict__ pe = sel ? pe_ee : pe_ss;
    float* __restrict__ outA     = sel ? g_Aee : g_Ass;

    // 16 rows x 128 floats = 16 rows x 32 ulonglong2 (8 KB).
    __shared__ ulonglong2 pe_sm[16][32];

    // Stage rows (vectorized 16B loads); zero-fill past end of table.
    const ulonglong2* __restrict__ peg = reinterpret_cast<const ulonglong2*>(pe);
    #pragma unroll
    for (int q = 0; q < 4; q++) {
        const int lin = q * 128 + h;       // 0..511
        const int r   = lin >> 5;
        const int c   = lin & 31;
        const int t   = t0 + r;
        ulonglong2 v;
        if (t < TABLE_ROWS) v = peg[(size_t)t * 32 + c];
        else { v.x = 0ULL; v.y = 0ULL; }
        pe_sm[r][c] = v;
    }
    __syncthreads();

    unsigned long long acc[16];
    #pragma unroll
    for (int r = 0; r < 16; r++) acc[r] = 0ULL;

    // W is [H, 2H] row-major; thread h uses W[h, sel*128 : sel*128+128],
    // viewed as 32 x ulonglong2 (each ull = one packed f32 pair).
    const ulonglong2* __restrict__ W2 = reinterpret_cast<const ulonglong2*>(
        W + (size_t)h * (2 * HIDDEN) + sel * HIDDEN);

    #pragma unroll 4
    for (int kg = 0; kg < 32; kg++) {
        const ulonglong2 w = W2[kg];
        #pragma unroll
        for (int r = 0; r < 16; r++) {
            const ulonglong2 p = pe_sm[r][kg];   // broadcast across warp
            FFMA2(acc[r], w.x, p.x);
            FFMA2(acc[r], w.y, p.y);
        }
    }

    const float binit = sel ? 0.0f : bias[h];
    #pragma unroll
    for (int r = 0; r < 16; r++) {
        const int t = t0 + r;
        if (t < TABLE_ROWS) {
            float lo, hi;
            asm("mov.b64 {%0, %1}, %2;" : "=f"(lo), "=f"(hi) : "l"(acc[r]));
            outA[(size_t)t * HIDDEN + h] = lo + hi + binit;
        }
    }
}

// ---------------------------------------------------------------------------
// Kernel 2: out[b,i,j,:] = relu(A_ss[ps[i]-ps[j]+512] + A_ee[pe[i]-pe[j]+512])
// grid = B*SEQ blocks (one per (b,i)), block = 256 threads = 8 warps.
// Position rows cached in SMEM; one warp per j-row; float4 gather + store.
// (R1 configuration: regs=32, occ 74% — measured best.)
// ---------------------------------------------------------------------------
__global__ void __launch_bounds__(256)
fuse_gather_kernel(const int* __restrict__ pos_s,
                   const int* __restrict__ pos_e,
                   float* __restrict__ out)
{
    const int bi = blockIdx.x;          // b*SEQ + i
    const int b  = bi >> 9;
    const int i  = bi & (SEQ - 1);

    __shared__ int ps_sm[SEQ];
    __shared__ int pe_sm[SEQ];
    for (int j = threadIdx.x; j < SEQ; j += blockDim.x) {
        ps_sm[j] = pos_s[b * SEQ + j];
        pe_sm[j] = pos_e[b * SEQ + j];
    }
    __syncthreads();

    const int psi = ps_sm[i];
    const int pei = pe_sm[i];

    const int warp = threadIdx.x >> 5;
    const int lane = threadIdx.x & 31;

    const float4* __restrict__ Ass4 = reinterpret_cast<const float4*>(g_Ass);
    const float4* __restrict__ Aee4 = reinterpret_cast<const float4*>(g_Aee);
    float4* __restrict__ out4 =
        reinterpret_cast<float4*>(out + (size_t)bi * SEQ * HIDDEN);

    for (int j = warp; j < SEQ; j += 8) {
        const int iss = psi - ps_sm[j] + MAXSEQ;   // in [1, 1023]
        const int iee = pei - pe_sm[j] + MAXSEQ;

        const float4 a = Ass4[iss * (HIDDEN / 4) + lane];
        const float4 e = Aee4[iee * (HIDDEN / 4) + lane];

        float4 r;
        r.x = fmaxf(a.x + e.x, 0.0f);
        r.y = fmaxf(a.y + e.y, 0.0f);
        r.z = fmaxf(a.z + e.z, 0.0f);
        r.w = fmaxf(a.w + e.w, 0.0f);

        out4[j * (HIDDEN / 4) + lane] = r;
    }
}

// ---------------------------------------------------------------------------
// Inputs (metadata order): 0 pos_s [B,S] i32, 1 pos_e [B,S] i32,
// 2 pe_ss [1025,128] f32, 3 pe_se (unused), 4 pe_es (unused),
// 5 pe_ee [1025,128] f32, 6 W [128,256] f32, 7 b [128] f32.
// Output: [B,S,S,H] f32.
// ---------------------------------------------------------------------------
extern "C" void kernel_launch(void* const* d_in, const int* in_sizes, int n_in,
                              void* d_out, int out_size)
{
    const int*   pos_s = (const int*)d_in[0];
    const int*   pos_e = (const int*)d_in[1];
    const float* pe_ss = (const float*)d_in[2];
    const float* pe_ee = (const float*)d_in[5];
    const float* W     = (const float*)d_in[6];
    const float* bias  = (const float*)d_in[7];
    float*       out   = (float*)d_out;

    dim3 grid1((TABLE_ROWS + 15) / 16, 2);
    project_tables_kernel<<<grid1, 128>>>(pe_ss, pe_ee, W, bias);

    fuse_gather_kernel<<<BATCH * SEQ, 256>>>(pos_s, pos_e, out);
}